// round 16
// baseline (speedup 1.0000x reference)
#include <cuda_runtime.h>
#include <cuda_fp16.h>
#include <cstdint>

// =====================================================================
// LocalRNN: B=8, L=2048, D=256, KSIZE=8   (sm_103 portable HMMA path)
// R16: base = R14 (best 66.3us, m64xn32 warps). Per-step __syncthreads
//      replaced by fine-grained column-ownership mbarriers:
//        RD[j] (8x32 arrives): all warps' A-reads of cols 32j..32j+31
//                              done -> warp j may write (epilogue).
//        WD[j] (32 arrives):   warp j's epilogue writes done -> others
//                              may A-read chunk pair j next step.
//      Warps pipeline across step boundaries (skew bounded by W ring).
//      Numerics bit-identical (rel_err 3.329e-4).
// SMEM:  [U 38016)[X|H 38016)[ring 2x16384)  = 108800 -> 2 CTAs/SM
// =====================================================================

namespace {
constexpr int Ll = 2048, Dd = 256, Ks = 8, ROWS = 16384;
constexpr int NCH  = 16;               // k-chunks of 16
constexpr int WCH  = 8192;             // packed chunk image: 256n x 32B
constexpr int GRPB = 2 * WCH;          // group = 2 chunks = 16384 B
constexpr int HSTR = 264;              // row stride in halfs (padded)
constexpr int TM   = 64;               // output rows per CTA
constexpr int NT   = 256;              // 8 warps, n-slice 32 each
constexpr int UROWS = 72;
constexpr int UIMG  = UROWS * HSTR * 2;            // 38016
constexpr int XOFF  = UIMG;
constexpr int HOFF  = UIMG;
constexpr int RINGOFF = XOFF + UIMG;               // 76032
constexpr int SMEM_DYN = RINGOFF + 2 * GRPB;       // 108800
constexpr int GTOT = (Ks - 1) * NCH;               // 112 W chunk-uses
}

__device__ __align__(16) __half g_Wf[NCH * 4096];
__device__ __align__(16) __half g_WIf[NCH * 4096];
__device__ float g_itau[Dd];

// ------------------------- PTX helpers --------------------------------
__device__ __forceinline__ uint32_t smem_u32(const void* p) {
    uint32_t a;
    asm("{ .reg .u64 t; cvta.to.shared.u64 t, %1; cvt.u32.u64 %0, t; }"
        : "=r"(a) : "l"(p));
    return a;
}

#define MBARRIER_INIT(mbar, cnt) \
    asm volatile("mbarrier.init.shared.b64 [%0], %1;" \
                 :: "r"((uint32_t)(mbar)), "r"((uint32_t)(cnt)) : "memory")
#define MBARRIER_ARRIVE(mbar) \
    asm volatile("mbarrier.arrive.shared.b64 _, [%0];" \
                 :: "r"((uint32_t)(mbar)) : "memory")
#define MBARRIER_EXPECT_TX(mbar, bytes) \
    asm volatile("mbarrier.arrive.expect_tx.shared.b64 _, [%0], %1;" \
                 :: "r"((uint32_t)(mbar)), "r"((uint32_t)(bytes)) : "memory")
#define MBARRIER_WAIT_PARITY(mbar, parity) do {                               \
    uint32_t _m = (uint32_t)(mbar);                                           \
    uint32_t _p = (uint32_t)(parity);                                         \
    uint32_t _done;                                                           \
    asm volatile(                                                             \
        "{\n\t.reg .pred p;\n\t"                                              \
        "mbarrier.try_wait.parity.acquire.cta.shared::cta.b64 p, [%1], %2;\n\t" \
        "selp.b32 %0, 1, 0, p;\n\t}"                                          \
        : "=r"(_done) : "r"(_m), "r"(_p) : "memory");                         \
    if (!_done) {                                                             \
        asm volatile(                                                         \
            "{\n\t.reg .pred P1;\n\t"                                         \
            "WL_%=:\n\t"                                                      \
            "mbarrier.try_wait.parity.acquire.cta.shared::cta.b64 P1, [%0], %1, 0x989680;\n\t" \
            "@P1 bra.uni WD_%=;\n\t"                                          \
            "bra.uni WL_%=;\n\t"                                              \
            "WD_%=:\n\t}"                                                     \
            :: "r"(_m), "r"(_p) : "memory");                                  \
    }                                                                         \
} while (0)

#define BULK_G2S(dst, src, bytes, mbar)                                       \
    asm volatile(                                                             \
        "cp.async.bulk.shared::cluster.global.mbarrier::complete_tx::bytes "  \
        "[%0], [%1], %2, [%3];"                                               \
        :: "r"((uint32_t)(dst)), "l"(src), "r"((uint32_t)(bytes)),            \
           "r"((uint32_t)(mbar)) : "memory")

#define LDSM_X4(r, addr)                                                      \
    asm volatile("ldmatrix.sync.aligned.m8n8.x4.shared.b16 "                  \
                 "{%0,%1,%2,%3}, [%4];"                                       \
                 : "=r"((r)[0]), "=r"((r)[1]), "=r"((r)[2]), "=r"((r)[3])     \
                 : "r"(addr))

#define MMAH(d, a, b0_, b1_)                                                  \
    asm volatile(                                                             \
        "mma.sync.aligned.m16n8k16.row.col.f32.f16.f16.f32 "                  \
        "{%0,%1,%2,%3},{%4,%5,%6,%7},{%8,%9},{%0,%1,%2,%3};"                  \
        : "+f"((d)[0]), "+f"((d)[1]), "+f"((d)[2]), "+f"((d)[3])              \
        : "r"((a)[0]), "r"((a)[1]), "r"((a)[2]), "r"((a)[3]),                 \
          "r"(b0_), "r"(b1_))

__device__ __forceinline__ uint32_t pack_hi(float x, float y) {
    __half2 p = __floats2half2_rn(x, y);
    return *(uint32_t*)&p;
}

// ====================== k0: W prep (float4 loads) =====================
__global__ __launch_bounds__(256) void w_prep_kernel(const float* __restrict__ W,
                                                     const float* __restrict__ Win,
                                                     const float* __restrict__ tau) {
    __shared__ float tile[16][256];
    const int c   = blockIdx.x >> 1;
    const int m   = blockIdx.x & 1;
    const int tid = threadIdx.x;
    const float* src = m ? Win : W;
    __half* dst = m ? g_WIf : g_Wf;
    if (blockIdx.x == 0 && tid < Dd) g_itau[tid] = 1.0f / tau[tid];

#pragma unroll
    for (int q = 0; q < 4; q++) {
        int idx = tid + q * 256;
        int kk = idx >> 6, c4 = (idx & 63) * 4;
        *(float4*)&tile[kk][c4] =
            *(const float4*)&src[(size_t)(c * 16 + kk) * Dd + c4];
    }
    __syncthreads();

    const uint32_t nsw = ((uint32_t)(tid >> 2) & 1u);
#pragma unroll
    for (int kh = 0; kh < 2; kh++) {
        uint32_t off = (uint32_t)c * 8192u + (uint32_t)tid * 32u +
                       (((uint32_t)kh ^ nsw) << 4);
        __half h8[8];
#pragma unroll
        for (int j = 0; j < 8; j++)
            h8[j] = __float2half_rn(tile[kh * 8 + j][tid]);
        *(uint4*)((char*)dst + off) = *(uint4*)h8;
    }
}

// ====================== k1: fused U-GEMM + RNN ========================
__global__ __launch_bounds__(NT, 2) void fused_kernel(const float* __restrict__ X,
                                                      const float* __restrict__ bias,
                                                      float* __restrict__ out) {
    extern __shared__ __align__(128) char dsmem[];
    __shared__ __align__(8) uint64_t s_wif[2], s_wie[2];
    __shared__ __align__(8) uint64_t s_wf[2],  s_we[2];
    __shared__ __align__(8) uint64_t s_rd[8];
    __shared__ __align__(8) uint64_t s_wd[8];

    const int tid = threadIdx.x;
    const int wid = tid >> 5;           // 0..7 -> n-slice wid*32
    const int t   = tid & 31;

    const uint32_t base = smem_u32(dsmem);
    const uint32_t xs   = base + XOFF;
    const uint32_t hs   = base + HOFF;
    const uint32_t ring = base + RINGOFF;
    const uint32_t mwf = smem_u32(s_wif), mwe = smem_u32(s_wie);
    const uint32_t mf  = smem_u32(s_wf),  me  = smem_u32(s_we);
    const uint32_t mrd = smem_u32(s_rd),  mwd = smem_u32(s_wd);
    const int r0 = blockIdx.x * TM;

    if (tid == 0) {
        for (int i = 0; i < 2; i++) {
            MBARRIER_INIT(mwf + i * 8, 1);
            MBARRIER_INIT(mwe + i * 8, 8);
            MBARRIER_INIT(mf + i * 8, 1);
            MBARRIER_INIT(me + i * 8, 8);
        }
        for (int i = 0; i < 8; i++) {
            MBARRIER_INIT(mrd + i * 8, 256);
            MBARRIER_INIT(mwd + i * 8, 32);
        }
    }
    __syncthreads();

    if (tid == 0) {
#pragma unroll
        for (int s = 0; s < 2; s++) {
            MBARRIER_EXPECT_TX(mwf + s * 8, GRPB);
            BULK_G2S(ring + s * GRPB,       (const char*)g_WIf + (2 * s) * WCH,
                     WCH, mwf + s * 8);
            BULK_G2S(ring + s * GRPB + WCH, (const char*)g_WIf + (2 * s + 1) * WCH,
                     WCH, mwf + s * 8);
        }
    }

    // ---- load X rows 0..71, convert to fp16 ----
    for (int xi = wid; xi < UROWS; xi += 8) {
        long gxr = (long)r0 - 8 + xi;
        if (gxr < 0) gxr = 0;
        const float* xr = X + (size_t)gxr * Dd;
        const int c = t * 8;
        float4 v0 = *(const float4*)(xr + c);
        float4 v1 = *(const float4*)(xr + c + 4);
        uint32_t p[4] = {pack_hi(v0.x, v0.y), pack_hi(v0.z, v0.w),
                         pack_hi(v1.x, v1.y), pack_hi(v1.z, v1.w)};
        *(uint4*)(dsmem + XOFF + (size_t)(xi * HSTR + c) * 2) = *(uint4*)p;
    }
    __syncthreads();

    const int a_r  = ((t >> 3) & 1) * 8 + (t & 7);
    const int a_k  = ((t >> 4) & 1) * 8;
    const int b_n  = ((t >> 4) & 1) * 8 + (t & 7);
    const int kh   = (t >> 3) & 1;
    const int nbase = wid * 32 + b_n;
    const uint32_t sw16 = ((((uint32_t)nbase >> 2) & 1u) ^ (uint32_t)kh) << 4;
    const uint32_t boff = (uint32_t)nbase * 32 + sw16;

    // =================== Phase A: U = X @ Win + bias ==================
    {
        float D[4][4][4];
        float Ds[4][4];
#pragma unroll
        for (int i = 0; i < 4; i++)
#pragma unroll
            for (int j = 0; j < 4; j++)
#pragma unroll
                for (int q = 0; q < 4; q++) D[i][j][q] = 0.f;
#pragma unroll
        for (int j = 0; j < 4; j++)
#pragma unroll
            for (int q = 0; q < 4; q++) Ds[j][q] = 0.f;

        for (int g = 0; g < NCH; g++) {
            const int G = g >> 1;
            if ((g & 1) == 0)
                MBARRIER_WAIT_PARITY(mwf + (G & 1) * 8, (G >> 1) & 1);

            uint32_t AH[4][4], As[4];
            const int kc = g * 16;
#pragma unroll
            for (int i = 0; i < 4; i++) {
                uint32_t off =
                    (uint32_t)((8 + i * 16 + a_r) * HSTR + kc + a_k) * 2;
                LDSM_X4(AH[i], xs + off);
            }
            LDSM_X4(As, xs + (uint32_t)(a_r * HSTR + kc + a_k) * 2);

            const uint32_t sb = ring + (uint32_t)(G & 1) * GRPB +
                                (uint32_t)(g & 1) * WCH;
            uint32_t BH[2][4];
            LDSM_X4(BH[0], sb + boff);
            LDSM_X4(BH[1], sb + boff + 16 * 32);

            if (g & 1) {
                __syncwarp();
                if (t == 0) MBARRIER_ARRIVE(mwe + (G & 1) * 8);
                if (tid == 0 && G + 2 < 8) {
                    MBARRIER_WAIT_PARITY(mwe + (G & 1) * 8, (G >> 1) & 1);
                    const int cp = (G + 2) * 2;
                    MBARRIER_EXPECT_TX(mwf + (G & 1) * 8, GRPB);
                    BULK_G2S(ring + (G & 1) * GRPB,
                             (const char*)g_WIf + cp * WCH, WCH,
                             mwf + (G & 1) * 8);
                    BULK_G2S(ring + (G & 1) * GRPB + WCH,
                             (const char*)g_WIf + (cp + 1) * WCH, WCH,
                             mwf + (G & 1) * 8);
                }
            }

#pragma unroll
            for (int jp = 0; jp < 2; jp++) {
#pragma unroll
                for (int i = 0; i < 4; i++) {
                    MMAH(D[i][2 * jp],     AH[i], BH[jp][0], BH[jp][1]);
                    MMAH(D[i][2 * jp + 1], AH[i], BH[jp][2], BH[jp][3]);
                }
                MMAH(Ds[2 * jp],     As, BH[jp][0], BH[jp][1]);
                MMAH(Ds[2 * jp + 1], As, BH[jp][2], BH[jp][3]);
            }
        }

#pragma unroll
        for (int i = 0; i < 4; i++) {
#pragma unroll
            for (int half = 0; half < 2; half++) {
                const int ru = 8 + i * 16 + (t >> 2) + half * 8;
#pragma unroll
                for (int j = 0; j < 4; j++) {
                    const int cc = wid * 32 + j * 8 + 2 * (t & 3);
                    float2 b = *(const float2*)(bias + cc);
                    *(uint32_t*)(dsmem + (size_t)(ru * HSTR + cc) * 2) =
                        pack_hi(D[i][j][half * 2] + b.x,
                                D[i][j][half * 2 + 1] + b.y);
                }
            }
        }
#pragma unroll
        for (int half = 0; half < 2; half++) {
            const int ru = (t >> 2) + half * 8;
#pragma unroll
            for (int j = 0; j < 4; j++) {
                const int cc = wid * 32 + j * 8 + 2 * (t & 3);
                float2 b = *(const float2*)(bias + cc);
                *(uint32_t*)(dsmem + (size_t)(ru * HSTR + cc) * 2) =
                    pack_hi(Ds[j][half * 2] + b.x,
                            Ds[j][half * 2 + 1] + b.y);
            }
        }
    }
    __syncthreads();

    if (tid == 0) {
#pragma unroll
        for (int s = 0; s < 2; s++) {
            MBARRIER_EXPECT_TX(mf + s * 8, GRPB);
            BULK_G2S(ring + s * GRPB,       (const char*)g_Wf + (2 * s) * WCH,
                     WCH, mf + s * 8);
            BULK_G2S(ring + s * GRPB + WCH, (const char*)g_Wf + (2 * s + 1) * WCH,
                     WCH, mf + s * 8);
        }
    }

    // ---- step 0: h1 = itau * relu(u_{l-7}) ----
    for (int rr = wid; rr < TM; rr += 8) {
        const int gr = r0 + rr;
        const int l  = gr & (Ll - 1);
        const int c  = t * 8;
        float u[8];
        if (l >= Ks - 1) {
            uint4 up = *(uint4*)(dsmem + (size_t)((rr + 1) * HSTR + c) * 2);
            uint32_t uw[4] = {up.x, up.y, up.z, up.w};
#pragma unroll
            for (int q = 0; q < 4; q++) {
                __half2 h2 = *(__half2*)&uw[q];
                u[2 * q]     = __half2float(__low2half(h2));
                u[2 * q + 1] = __half2float(__high2half(h2));
            }
        } else {
            float4 b0 = *(const float4*)(bias + c);
            float4 b1 = *(const float4*)(bias + c + 4);
            u[0] = b0.x; u[1] = b0.y; u[2] = b0.z; u[3] = b0.w;
            u[4] = b1.x; u[5] = b1.y; u[6] = b1.z; u[7] = b1.w;
        }
        float4 i0 = *(const float4*)(g_itau + c);
        float4 i1 = *(const float4*)(g_itau + c + 4);
        float it[8] = {i0.x, i0.y, i0.z, i0.w, i1.x, i1.y, i1.z, i1.w};
        uint32_t p[4];
#pragma unroll
        for (int q = 0; q < 4; q++)
            p[q] = pack_hi(it[2 * q] * fmaxf(u[2 * q], 0.f),
                           it[2 * q + 1] * fmaxf(u[2 * q + 1], 0.f));
        *(uint4*)(dsmem + HOFF + (size_t)(rr * HSTR + c) * 2) = *(uint4*)p;
    }
    __syncthreads();   // H(step0) visible; guards step-1 A reads

    // =================== Phase B: 7-step recurrence ===================
    int gg = 0;
    for (int step = 1; step < Ks; step++) {
        const bool last = (step == Ks - 1);
        float D[4][4][4];
#pragma unroll
        for (int i = 0; i < 4; i++)
#pragma unroll
            for (int j = 0; j < 4; j++)
#pragma unroll
                for (int q = 0; q < 4; q++) D[i][j][q] = 0.f;

        uint32_t BH[2][2][4];

        {
            const int G = gg >> 1;
            MBARRIER_WAIT_PARITY(mf + (G & 1) * 8, (G >> 1) & 1);
            const uint32_t sb = ring + (uint32_t)(G & 1) * GRPB;
            LDSM_X4(BH[0][0], sb + boff);
            LDSM_X4(BH[0][1], sb + boff + 16 * 32);
        }

        for (int c = 0; c < NCH; c++, gg++) {
            const int cur = c & 1;
            if (c < NCH - 1) {
                const int g1 = gg + 1;
                const int G1 = g1 >> 1;
                if ((g1 & 1) == 0)
                    MBARRIER_WAIT_PARITY(mf + (G1 & 1) * 8, (G1 >> 1) & 1);
                const uint32_t sb1 = ring + (uint32_t)(G1 & 1) * GRPB +
                                     (uint32_t)(g1 & 1) * WCH;
                LDSM_X4(BH[cur ^ 1][0], sb1 + boff);
                LDSM_X4(BH[cur ^ 1][1], sb1 + boff + 16 * 32);
                if (g1 & 1) {
                    __syncwarp();
                    if (t == 0) MBARRIER_ARRIVE(me + (G1 & 1) * 8);
                    if (tid == 0 && (G1 + 2) * 2 < GTOT) {
                        MBARRIER_WAIT_PARITY(me + (G1 & 1) * 8, (G1 >> 1) & 1);
                        const int cp = ((G1 + 2) * 2) & 15;
                        MBARRIER_EXPECT_TX(mf + (G1 & 1) * 8, GRPB);
                        BULK_G2S(ring + (G1 & 1) * GRPB,
                                 (const char*)g_Wf + cp * WCH, WCH,
                                 mf + (G1 & 1) * 8);
                        BULK_G2S(ring + (G1 & 1) * GRPB + WCH,
                                 (const char*)g_Wf + (cp + 1) * WCH, WCH,
                                 mf + (G1 & 1) * 8);
                    }
                }
            }

            if (step >= 2 && (c & 1) == 0)
                MBARRIER_WAIT_PARITY(mwd + (c >> 1) * 8, (step - 2) & 1);

            uint32_t AH[4][4];
            const int kc = c * 16;
#pragma unroll
            for (int i = 0; i < 4; i++) {
                uint32_t off =
                    (uint32_t)((i * 16 + a_r) * HSTR + kc + a_k) * 2;
                LDSM_X4(AH[i], hs + off);
            }
            if ((c & 1) && !last)
                MBARRIER_ARRIVE(mrd + (c >> 1) * 8);

#pragma unroll
            for (int jp = 0; jp < 2; jp++)
#pragma unroll
                for (int i = 0; i < 4; i++) {
                    MMAH(D[i][2 * jp],     AH[i], BH[cur][jp][0], BH[cur][jp][1]);
                    MMAH(D[i][2 * jp + 1], AH[i], BH[cur][jp][2], BH[cur][jp][3]);
                }
        }

        if (!last)
            MBARRIER_WAIT_PARITY(mrd + wid * 8, (step - 1) & 1);

#pragma unroll
        for (int i = 0; i < 4; i++) {
#pragma unroll
            for (int half = 0; half < 2; half++) {
                const int rl = i * 16 + (t >> 2) + half * 8;
                const int gr = r0 + rl;
                const int tt = (gr & (Ll - 1)) - (Ks - 1) + step;
                const int ur = rl + step + 1;
#pragma unroll
                for (int j = 0; j < 4; j++) {
                    const int cc = wid * 32 + j * 8 + 2 * (t & 3);
                    float2 u;
                    if (tt >= 0) {
                        uint32_t uv =
                            *(uint32_t*)(dsmem + (size_t)(ur * HSTR + cc) * 2);
                        __half2 uh = *(__half2*)&uv;
                        u = make_float2(__half2float(__low2half(uh)),
                                        __half2float(__high2half(uh)));
                    } else {
                        u = *(const float2*)(bias + cc);
                    }
                    float2 it = *(const float2*)(g_itau + cc);
                    const float d0 = D[i][j][half * 2];
                    const float d1 = D[i][j][half * 2 + 1];
                    char* hb = dsmem + HOFF + (size_t)(rl * HSTR + cc) * 2;
                    uint32_t hv = *(uint32_t*)(hb);
                    __half2 hh = *(__half2*)&hv;
                    float h0 = __half2float(__low2half(hh));
                    float h1 = __half2float(__high2half(hh));
                    float s0 = fmaxf(d0 + u.x, 0.f);
                    float s1 = fmaxf(d1 + u.y, 0.f);
                    float n0 = h0 + it.x * (s0 - h0);
                    float n1 = h1 + it.y * (s1 - h1);
                    if (last) {
                        *(float2*)(out + (size_t)gr * Dd + cc) =
                            make_float2(n0, n1);
                    } else {
                        *(uint32_t*)(hb) = pack_hi(n0, n1);
                    }
                }
            }
        }
        if (!last)
            MBARRIER_ARRIVE(mwd + wid * 8);
    }
}

// ---------------------------------------------------------------------------
extern "C" void kernel_launch(void* const* d_in, const int* in_sizes, int n_in,
                              void* d_out, int out_size) {
    (void)in_sizes; (void)n_in; (void)out_size;
    const float* x            = (const float*)d_in[0];
    const float* weight       = (const float*)d_in[1];
    const float* input_weight = (const float*)d_in[2];
    const float* bias         = (const float*)d_in[3];
    const float* tau          = (const float*)d_in[4];
    float* out = (float*)d_out;

    w_prep_kernel<<<2 * NCH, 256>>>(weight, input_weight, tau);

    cudaFuncSetAttribute(fused_kernel, cudaFuncAttributeMaxDynamicSharedMemorySize,
                         SMEM_DYN);
    fused_kernel<<<ROWS / TM, NT, SMEM_DYN>>>(x, bias, out);
}

// round 17
// speedup vs baseline: 1.4375x; 1.4375x over previous
#include <cuda_runtime.h>
#include <cuda_fp16.h>
#include <cstdint>

// =====================================================================
// LocalRNN: B=8, L=2048, D=256, KSIZE=8   (sm_103 portable HMMA path)
// R17: revert to R14 (best 66.3us) + micro-opts only:
//      (1) w_prep split to 128 blocks (64-wide n-slices) ~2x faster,
//      (2) drop redundant __syncwarp before empty-arrives (ldmatrix.sync
//          is already warp-collective),
//      (3) epilogue u-loads batched 4-wide (MLP) before compute.
//      Structure/numerics identical to R14 (rel_err 3.329e-4).
// SMEM:  [U 38016)[X|H 38016)[ring 2x16384)  = 108800 -> 2 CTAs/SM
// =====================================================================

namespace {
constexpr int Ll = 2048, Dd = 256, Ks = 8, ROWS = 16384;
constexpr int NCH  = 16;               // k-chunks of 16
constexpr int WCH  = 8192;             // packed chunk image: 256n x 32B
constexpr int GRPB = 2 * WCH;          // group = 2 chunks = 16384 B
constexpr int HSTR = 264;              // row stride in halfs (padded)
constexpr int TM   = 64;               // output rows per CTA
constexpr int NT   = 256;              // 8 warps, n-slice 32 each
constexpr int UROWS = 72;              // U rows incl. 8 boundary rows
constexpr int UIMG  = UROWS * HSTR * 2;            // 38016
constexpr int XOFF  = UIMG;
constexpr int HOFF  = UIMG;
constexpr int RINGOFF = XOFF + UIMG;               // 76032
constexpr int SMEM_DYN = RINGOFF + 2 * GRPB;       // 108800
constexpr int GTOT = (Ks - 1) * NCH;               // 112 W chunk-uses
}

__device__ __align__(16) __half g_Wf[NCH * 4096];
__device__ __align__(16) __half g_WIf[NCH * 4096];
__device__ float g_itau[Dd];

// ------------------------- PTX helpers --------------------------------
__device__ __forceinline__ uint32_t smem_u32(const void* p) {
    uint32_t a;
    asm("{ .reg .u64 t; cvta.to.shared.u64 t, %1; cvt.u32.u64 %0, t; }"
        : "=r"(a) : "l"(p));
    return a;
}

#define MBARRIER_INIT(mbar, cnt) \
    asm volatile("mbarrier.init.shared.b64 [%0], %1;" \
                 :: "r"((uint32_t)(mbar)), "r"((uint32_t)(cnt)) : "memory")
#define MBARRIER_ARRIVE(mbar) \
    asm volatile("mbarrier.arrive.shared.b64 _, [%0];" \
                 :: "r"((uint32_t)(mbar)) : "memory")
#define MBARRIER_EXPECT_TX(mbar, bytes) \
    asm volatile("mbarrier.arrive.expect_tx.shared.b64 _, [%0], %1;" \
                 :: "r"((uint32_t)(mbar)), "r"((uint32_t)(bytes)) : "memory")
#define MBARRIER_WAIT_PARITY(mbar, parity) do {                               \
    uint32_t _m = (uint32_t)(mbar);                                           \
    uint32_t _p = (uint32_t)(parity);                                         \
    uint32_t _done;                                                           \
    asm volatile(                                                             \
        "{\n\t.reg .pred p;\n\t"                                              \
        "mbarrier.try_wait.parity.acquire.cta.shared::cta.b64 p, [%1], %2;\n\t" \
        "selp.b32 %0, 1, 0, p;\n\t}"                                          \
        : "=r"(_done) : "r"(_m), "r"(_p) : "memory");                         \
    if (!_done) {                                                             \
        asm volatile(                                                         \
            "{\n\t.reg .pred P1;\n\t"                                         \
            "WL_%=:\n\t"                                                      \
            "mbarrier.try_wait.parity.acquire.cta.shared::cta.b64 P1, [%0], %1, 0x989680;\n\t" \
            "@P1 bra.uni WD_%=;\n\t"                                          \
            "bra.uni WL_%=;\n\t"                                              \
            "WD_%=:\n\t}"                                                     \
            :: "r"(_m), "r"(_p) : "memory");                                  \
    }                                                                         \
} while (0)

#define BULK_G2S(dst, src, bytes, mbar)                                       \
    asm volatile(                                                             \
        "cp.async.bulk.shared::cluster.global.mbarrier::complete_tx::bytes "  \
        "[%0], [%1], %2, [%3];"                                               \
        :: "r"((uint32_t)(dst)), "l"(src), "r"((uint32_t)(bytes)),            \
           "r"((uint32_t)(mbar)) : "memory")

#define LDSM_X4(r, addr)                                                      \
    asm volatile("ldmatrix.sync.aligned.m8n8.x4.shared.b16 "                  \
                 "{%0,%1,%2,%3}, [%4];"                                       \
                 : "=r"((r)[0]), "=r"((r)[1]), "=r"((r)[2]), "=r"((r)[3])     \
                 : "r"(addr))

#define MMAH(d, a, b0_, b1_)                                                  \
    asm volatile(                                                             \
        "mma.sync.aligned.m16n8k16.row.col.f32.f16.f16.f32 "                  \
        "{%0,%1,%2,%3},{%4,%5,%6,%7},{%8,%9},{%0,%1,%2,%3};"                  \
        : "+f"((d)[0]), "+f"((d)[1]), "+f"((d)[2]), "+f"((d)[3])              \
        : "r"((a)[0]), "r"((a)[1]), "r"((a)[2]), "r"((a)[3]),                 \
          "r"(b0_), "r"(b1_))

__device__ __forceinline__ uint32_t pack_hi(float x, float y) {
    __half2 p = __floats2half2_rn(x, y);
    return *(uint32_t*)&p;
}

// ====================== k0: W prep (128 blocks) =======================
// Block b: c = b>>3, m = (b>>2)&1, nq = b&3 -> n in [nq*64, nq*64+64).
__global__ __launch_bounds__(256) void w_prep_kernel(const float* __restrict__ W,
                                                     const float* __restrict__ Win,
                                                     const float* __restrict__ tau) {
    __shared__ float tile[16][64];
    const int c   = blockIdx.x >> 3;
    const int m   = (blockIdx.x >> 2) & 1;
    const int nq  = blockIdx.x & 3;
    const int tid = threadIdx.x;
    const float* src = m ? Win : W;
    __half* dst = m ? g_WIf : g_Wf;
    if (blockIdx.x == 0 && tid < Dd) g_itau[tid] = 1.0f / tau[tid];

    // 16 rows x 64 cols = 1024 floats; 256 threads x 1 float4
    {
        int kk = tid >> 4, c4 = (tid & 15) * 4;
        *(float4*)&tile[kk][c4] =
            *(const float4*)&src[(size_t)(c * 16 + kk) * Dd + nq * 64 + c4];
    }
    __syncthreads();

    if (tid < 64) {
        const int n = nq * 64 + tid;
        const uint32_t nsw = ((uint32_t)(n >> 2) & 1u);
#pragma unroll
        for (int kh = 0; kh < 2; kh++) {
            uint32_t off = (uint32_t)c * 8192u + (uint32_t)n * 32u +
                           (((uint32_t)kh ^ nsw) << 4);
            __half h8[8];
#pragma unroll
            for (int j = 0; j < 8; j++)
                h8[j] = __float2half_rn(tile[kh * 8 + j][tid]);
            *(uint4*)((char*)dst + off) = *(uint4*)h8;
        }
    }
}

// ====================== k1: fused U-GEMM + RNN ========================
__global__ __launch_bounds__(NT, 2) void fused_kernel(const float* __restrict__ X,
                                                      const float* __restrict__ bias,
                                                      float* __restrict__ out) {
    extern __shared__ __align__(128) char dsmem[];
    __shared__ __align__(8) uint64_t s_wif[2], s_wie[2];
    __shared__ __align__(8) uint64_t s_wf[2],  s_we[2];

    const int tid = threadIdx.x;
    const int wid = tid >> 5;           // 0..7 -> n-slice wid*32
    const int t   = tid & 31;

    const uint32_t base = smem_u32(dsmem);
    const uint32_t xs   = base + XOFF;
    const uint32_t hs   = base + HOFF;
    const uint32_t ring = base + RINGOFF;
    const uint32_t mwf = smem_u32(s_wif), mwe = smem_u32(s_wie);
    const uint32_t mf  = smem_u32(s_wf),  me  = smem_u32(s_we);
    const int r0 = blockIdx.x * TM;

    if (tid == 0) {
        for (int i = 0; i < 2; i++) {
            MBARRIER_INIT(mwf + i * 8, 1);
            MBARRIER_INIT(mwe + i * 8, 8);
            MBARRIER_INIT(mf + i * 8, 1);
            MBARRIER_INIT(me + i * 8, 8);
        }
    }
    __syncthreads();

    // Prime phase-A ring: groups 0,1 (Win chunks 0..3)
    if (tid == 0) {
#pragma unroll
        for (int s = 0; s < 2; s++) {
            MBARRIER_EXPECT_TX(mwf + s * 8, GRPB);
            BULK_G2S(ring + s * GRPB,       (const char*)g_WIf + (2 * s) * WCH,
                     WCH, mwf + s * 8);
            BULK_G2S(ring + s * GRPB + WCH, (const char*)g_WIf + (2 * s + 1) * WCH,
                     WCH, mwf + s * 8);
        }
    }

    // ---- load X rows 0..71 (global r0-8+xi), convert to fp16 ----
    for (int xi = wid; xi < UROWS; xi += 8) {
        long gxr = (long)r0 - 8 + xi;
        if (gxr < 0) gxr = 0;                 // values unused when invalid
        const float* xr = X + (size_t)gxr * Dd;
        const int c = t * 8;
        float4 v0 = *(const float4*)(xr + c);
        float4 v1 = *(const float4*)(xr + c + 4);
        uint32_t p[4] = {pack_hi(v0.x, v0.y), pack_hi(v0.z, v0.w),
                         pack_hi(v1.x, v1.y), pack_hi(v1.z, v1.w)};
        *(uint4*)(dsmem + XOFF + (size_t)(xi * HSTR + c) * 2) = *(uint4*)p;
    }
    __syncthreads();

    const int a_r  = ((t >> 3) & 1) * 8 + (t & 7);
    const int a_k  = ((t >> 4) & 1) * 8;
    const int b_n  = ((t >> 4) & 1) * 8 + (t & 7);
    const int kh   = (t >> 3) & 1;
    const int nbase = wid * 32 + b_n;
    const uint32_t sw16 = ((((uint32_t)nbase >> 2) & 1u) ^ (uint32_t)kh) << 4;
    const uint32_t boff = (uint32_t)nbase * 32 + sw16;

    // =================== Phase A: U = X @ Win + bias ==================
    {
        float D[4][4][4];           // main m64 x n32
        float Ds[4][4];             // strip m16 x n32
#pragma unroll
        for (int i = 0; i < 4; i++)
#pragma unroll
            for (int j = 0; j < 4; j++)
#pragma unroll
                for (int q = 0; q < 4; q++) D[i][j][q] = 0.f;
#pragma unroll
        for (int j = 0; j < 4; j++)
#pragma unroll
            for (int q = 0; q < 4; q++) Ds[j][q] = 0.f;

        for (int g = 0; g < NCH; g++) {
            const int G = g >> 1;
            if ((g & 1) == 0)
                MBARRIER_WAIT_PARITY(mwf + (G & 1) * 8, (G >> 1) & 1);

            uint32_t AH[4][4], As[4];
            const int kc = g * 16;
#pragma unroll
            for (int i = 0; i < 4; i++) {
                uint32_t off =
                    (uint32_t)((8 + i * 16 + a_r) * HSTR + kc + a_k) * 2;
                LDSM_X4(AH[i], xs + off);
            }
            LDSM_X4(As, xs + (uint32_t)(a_r * HSTR + kc + a_k) * 2);

            const uint32_t sb = ring + (uint32_t)(G & 1) * GRPB +
                                (uint32_t)(g & 1) * WCH;
            uint32_t BH[2][4];
            LDSM_X4(BH[0], sb + boff);
            LDSM_X4(BH[1], sb + boff + 16 * 32);

            if (g & 1) {                     // group's ring reads done
                if (t == 0) MBARRIER_ARRIVE(mwe + (G & 1) * 8);
                if (tid == 0 && G + 2 < 8) {
                    MBARRIER_WAIT_PARITY(mwe + (G & 1) * 8, (G >> 1) & 1);
                    const int cp = (G + 2) * 2;
                    MBARRIER_EXPECT_TX(mwf + (G & 1) * 8, GRPB);
                    BULK_G2S(ring + (G & 1) * GRPB,
                             (const char*)g_WIf + cp * WCH, WCH,
                             mwf + (G & 1) * 8);
                    BULK_G2S(ring + (G & 1) * GRPB + WCH,
                             (const char*)g_WIf + (cp + 1) * WCH, WCH,
                             mwf + (G & 1) * 8);
                }
            }

#pragma unroll
            for (int jp = 0; jp < 2; jp++) {
#pragma unroll
                for (int i = 0; i < 4; i++) {
                    MMAH(D[i][2 * jp],     AH[i], BH[jp][0], BH[jp][1]);
                    MMAH(D[i][2 * jp + 1], AH[i], BH[jp][2], BH[jp][3]);
                }
                MMAH(Ds[2 * jp],     As, BH[jp][0], BH[jp][1]);
                MMAH(Ds[2 * jp + 1], As, BH[jp][2], BH[jp][3]);
            }
        }

        // ---- epilogue A: U = D + bias -> SMEM fp16 ----
#pragma unroll
        for (int i = 0; i < 4; i++) {
#pragma unroll
            for (int half = 0; half < 2; half++) {
                const int ru = 8 + i * 16 + (t >> 2) + half * 8;
#pragma unroll
                for (int j = 0; j < 4; j++) {
                    const int cc = wid * 32 + j * 8 + 2 * (t & 3);
                    float2 b = *(const float2*)(bias + cc);
                    *(uint32_t*)(dsmem + (size_t)(ru * HSTR + cc) * 2) =
                        pack_hi(D[i][j][half * 2] + b.x,
                                D[i][j][half * 2 + 1] + b.y);
                }
            }
        }
        // strip rows 0..15 (rows 8..15 double-written, identical bits)
#pragma unroll
        for (int half = 0; half < 2; half++) {
            const int ru = (t >> 2) + half * 8;
#pragma unroll
            for (int j = 0; j < 4; j++) {
                const int cc = wid * 32 + j * 8 + 2 * (t & 3);
                float2 b = *(const float2*)(bias + cc);
                *(uint32_t*)(dsmem + (size_t)(ru * HSTR + cc) * 2) =
                    pack_hi(Ds[j][half * 2] + b.x,
                            Ds[j][half * 2 + 1] + b.y);
            }
        }
    }
    __syncthreads();   // U complete; X + Win ring dead

    // Prime phase-B ring: groups 0,1 (W chunks 0..3)
    if (tid == 0) {
#pragma unroll
        for (int s = 0; s < 2; s++) {
            MBARRIER_EXPECT_TX(mf + s * 8, GRPB);
            BULK_G2S(ring + s * GRPB,       (const char*)g_Wf + (2 * s) * WCH,
                     WCH, mf + s * 8);
            BULK_G2S(ring + s * GRPB + WCH, (const char*)g_Wf + (2 * s + 1) * WCH,
                     WCH, mf + s * 8);
        }
    }

    // ---- step 0: h1 = itau * relu(u_{l-7})  (U image row rr+1) ----
    for (int rr = wid; rr < TM; rr += 8) {
        const int gr = r0 + rr;
        const int l  = gr & (Ll - 1);
        const int c  = t * 8;
        float u[8];
        if (l >= Ks - 1) {
            uint4 up = *(uint4*)(dsmem + (size_t)((rr + 1) * HSTR + c) * 2);
            uint32_t uw[4] = {up.x, up.y, up.z, up.w};
#pragma unroll
            for (int q = 0; q < 4; q++) {
                __half2 h2 = *(__half2*)&uw[q];
                u[2 * q]     = __half2float(__low2half(h2));
                u[2 * q + 1] = __half2float(__high2half(h2));
            }
        } else {
            float4 b0 = *(const float4*)(bias + c);
            float4 b1 = *(const float4*)(bias + c + 4);
            u[0] = b0.x; u[1] = b0.y; u[2] = b0.z; u[3] = b0.w;
            u[4] = b1.x; u[5] = b1.y; u[6] = b1.z; u[7] = b1.w;
        }
        float4 i0 = *(const float4*)(g_itau + c);
        float4 i1 = *(const float4*)(g_itau + c + 4);
        float it[8] = {i0.x, i0.y, i0.z, i0.w, i1.x, i1.y, i1.z, i1.w};
        uint32_t p[4];
#pragma unroll
        for (int q = 0; q < 4; q++)
            p[q] = pack_hi(it[2 * q] * fmaxf(u[2 * q], 0.f),
                           it[2 * q + 1] * fmaxf(u[2 * q + 1], 0.f));
        *(uint4*)(dsmem + HOFF + (size_t)(rr * HSTR + c) * 2) = *(uint4*)p;
    }
    __syncthreads();

    // =================== Phase B: 7-step recurrence ===================
    int gg = 0;   // continuous chunk counter 0..111
    for (int step = 1; step < Ks; step++) {
        float D[4][4][4];
#pragma unroll
        for (int i = 0; i < 4; i++)
#pragma unroll
            for (int j = 0; j < 4; j++)
#pragma unroll
                for (int q = 0; q < 4; q++) D[i][j][q] = 0.f;

        uint32_t BH[2][2][4];    // double-buffered B fragments

        // prologue: gg group-aligned -> even chunk
        {
            const int G = gg >> 1;
            MBARRIER_WAIT_PARITY(mf + (G & 1) * 8, (G >> 1) & 1);
            const uint32_t sb = ring + (uint32_t)(G & 1) * GRPB;
            LDSM_X4(BH[0][0], sb + boff);
            LDSM_X4(BH[0][1], sb + boff + 16 * 32);
        }

        for (int c = 0; c < NCH; c++, gg++) {
            const int cur = c & 1;
            // prefetch B for chunk gg+1
            if (c < NCH - 1) {
                const int g1 = gg + 1;
                const int G1 = g1 >> 1;
                if ((g1 & 1) == 0)
                    MBARRIER_WAIT_PARITY(mf + (G1 & 1) * 8, (G1 >> 1) & 1);
                const uint32_t sb1 = ring + (uint32_t)(G1 & 1) * GRPB +
                                     (uint32_t)(g1 & 1) * WCH;
                LDSM_X4(BH[cur ^ 1][0], sb1 + boff);
                LDSM_X4(BH[cur ^ 1][1], sb1 + boff + 16 * 32);
                if (g1 & 1) {        // loaded odd chunk -> group done
                    if (t == 0) MBARRIER_ARRIVE(me + (G1 & 1) * 8);
                    if (tid == 0 && (G1 + 2) * 2 < GTOT) {
                        MBARRIER_WAIT_PARITY(me + (G1 & 1) * 8, (G1 >> 1) & 1);
                        const int cp = ((G1 + 2) * 2) & 15;
                        MBARRIER_EXPECT_TX(mf + (G1 & 1) * 8, GRPB);
                        BULK_G2S(ring + (G1 & 1) * GRPB,
                                 (const char*)g_Wf + cp * WCH, WCH,
                                 mf + (G1 & 1) * 8);
                        BULK_G2S(ring + (G1 & 1) * GRPB + WCH,
                                 (const char*)g_Wf + (cp + 1) * WCH, WCH,
                                 mf + (G1 & 1) * 8);
                    }
                }
            }

            // A fragments for chunk c
            uint32_t AH[4][4];
            const int kc = c * 16;
#pragma unroll
            for (int i = 0; i < 4; i++) {
                uint32_t off =
                    (uint32_t)((i * 16 + a_r) * HSTR + kc + a_k) * 2;
                LDSM_X4(AH[i], hs + off);
            }

#pragma unroll
            for (int jp = 0; jp < 2; jp++)
#pragma unroll
                for (int i = 0; i < 4; i++) {
                    MMAH(D[i][2 * jp],     AH[i], BH[cur][jp][0], BH[cur][jp][1]);
                    MMAH(D[i][2 * jp + 1], AH[i], BH[cur][jp][2], BH[cur][jp][3]);
                }
        }
        __syncthreads();   // all A-reads of H done before epilogue writes

        // ---- fused epilogue: h' = h + itau*(relu(D+u) - h) ----
        const bool last = (step == Ks - 1);
#pragma unroll
        for (int i = 0; i < 4; i++) {
#pragma unroll
            for (int half = 0; half < 2; half++) {
                const int rl = i * 16 + (t >> 2) + half * 8;
                const int gr = r0 + rl;
                const int tt = (gr & (Ll - 1)) - (Ks - 1) + step;
                const int ur = rl + step + 1;      // U image row (<= 71)
                // batch u-loads (MLP=4), then compute
                uint32_t uv[4];
                if (tt >= 0) {
#pragma unroll
                    for (int j = 0; j < 4; j++) {
                        const int cc = wid * 32 + j * 8 + 2 * (t & 3);
                        uv[j] = *(uint32_t*)(dsmem + (size_t)(ur * HSTR + cc) * 2);
                    }
                }
#pragma unroll
                for (int j = 0; j < 4; j++) {
                    const int cc = wid * 32 + j * 8 + 2 * (t & 3);
                    float2 u;
                    if (tt >= 0) {
                        __half2 uh = *(__half2*)&uv[j];
                        u = make_float2(__half2float(__low2half(uh)),
                                        __half2float(__high2half(uh)));
                    } else {
                        u = *(const float2*)(bias + cc);
                    }
                    float2 it = *(const float2*)(g_itau + cc);
                    const float d0 = D[i][j][half * 2];
                    const float d1 = D[i][j][half * 2 + 1];
                    char* hb = dsmem + HOFF + (size_t)(rl * HSTR + cc) * 2;
                    uint32_t hv = *(uint32_t*)(hb);
                    __half2 hh = *(__half2*)&hv;
                    float h0 = __half2float(__low2half(hh));
                    float h1 = __half2float(__high2half(hh));
                    float s0 = fmaxf(d0 + u.x, 0.f);
                    float s1 = fmaxf(d1 + u.y, 0.f);
                    float n0 = h0 + it.x * (s0 - h0);
                    float n1 = h1 + it.y * (s1 - h1);
                    if (last) {
                        *(float2*)(out + (size_t)gr * Dd + cc) =
                            make_float2(n0, n1);
                    } else {
                        *(uint32_t*)(hb) = pack_hi(n0, n1);
                    }
                }
            }
        }
        if (!last) __syncthreads();
    }
}

// ---------------------------------------------------------------------------
extern "C" void kernel_launch(void* const* d_in, const int* in_sizes, int n_in,
                              void* d_out, int out_size) {
    (void)in_sizes; (void)n_in; (void)out_size;
    const float* x            = (const float*)d_in[0];
    const float* weight       = (const float*)d_in[1];
    const float* input_weight = (const float*)d_in[2];
    const float* bias         = (const float*)d_in[3];
    const float* tau          = (const float*)d_in[4];
    float* out = (float*)d_out;

    w_prep_kernel<<<8 * NCH, 256>>>(weight, input_weight, tau);

    cudaFuncSetAttribute(fused_kernel, cudaFuncAttributeMaxDynamicSharedMemorySize,
                         SMEM_DYN);
    fused_kernel<<<ROWS / TM, NT, SMEM_DYN>>>(x, bias, out);
}